// round 14
// baseline (speedup 1.0000x reference)
#include <cuda_runtime.h>
#include <cstdint>

#define NPROP 8192
#define HID   512
#define NCTA  16          // cluster size for the scan
#define NTHR  384         // 12 warps, unified (warp 0 also does act+send)

// ---------------- scratch (static device arrays; no runtime alloc) ----------
__device__ float g_conv [(size_t)NPROP * 512];      // conv output, padded 504->512
__device__ float g_feats[(size_t)NPROP * 512];
__device__ float g_Gi   [(size_t)NPROP * 1536];     // reused for encoder then decoder
__device__ float g_hs   [(size_t)NPROP * 512];      // h per step (decoder) / final (enc)
__device__ float g_decin[(size_t)NPROP * 512];
__device__ float g_WaxPad[512 * 512];               // W_axis padded 504 -> 512 cols

// ---------------- helpers ---------------------------------------------------
__device__ __forceinline__ void fma2(unsigned long long& acc, unsigned long long a,
                                     unsigned long long b) {
    asm("fma.rn.f32x2 %0, %1, %2, %0;" : "+l"(acc) : "l"(a), "l"(b));
}
__device__ __forceinline__ unsigned long long pack2(float lo, float hi) {
    unsigned long long v;
    asm("mov.b64 %0, {%1, %2};" : "=l"(v) : "f"(lo), "f"(hi));
    return v;
}
__device__ __forceinline__ float2 unpack2(unsigned long long v) {
    float2 r; asm("mov.b64 {%0,%1}, %2;" : "=f"(r.x), "=f"(r.y) : "l"(v)); return r;
}
// accurate sigmoid (out_kernel, off critical path)
__device__ __forceinline__ float sigm(float x) {
    float e = __expf(-x);
    return __fdividef(1.f, 1.f + e);
}
// fast tanh (scan critical path): single MUFU.TANH
__device__ __forceinline__ float tanh_fast(float x) {
    float y;
    asm("tanh.approx.f32 %0, %1;" : "=f"(y) : "f"(x));
    return y;
}
__device__ __forceinline__ uint32_t smem_u32(const void* p) {
    uint32_t a;
    asm("{ .reg .u64 t; cvta.to.shared.u64 t, %1; cvt.u32.u64 %0, t; }" : "=r"(a) : "l"(p));
    return a;
}
__device__ __forceinline__ uint32_t mapa_u32(uint32_t local, uint32_t rank) {
    uint32_t r;
    asm("mapa.shared::cluster.u32 %0, %1, %2;" : "=r"(r) : "r"(local), "r"(rank));
    return r;
}
// local-scope acquire wait (data arrives via st.async + complete_tx)
__device__ __forceinline__ void mbar_wait_cta(uint32_t mbar, unsigned parity) {
    asm volatile(
        "{\n\t.reg .pred P;\n\t"
        "WLOOP_%=:\n\t"
        "mbarrier.try_wait.parity.acquire.cta.shared::cta.b64 P, [%0], %1, 0x989680;\n\t"
        "@P bra.uni WDONE_%=;\n\t"
        "bra.uni WLOOP_%=;\n\t"
        "WDONE_%=:\n\t}"
        :: "r"(mbar), "r"(parity) : "memory");
}

// ---------------- conv: [N,81,4,4] (x) [56,81,2,2] -> [N,504] (+pad to 512) --
__global__ void conv_kernel(const float* __restrict__ x, const float* __restrict__ Wc,
                            const float* __restrict__ bc) {
    __shared__ float xs[1296];
    const int n = blockIdx.x;
    const float4* xp = (const float4*)(x + (size_t)n * 1296);
    for (int i = threadIdx.x; i < 324; i += 64) ((float4*)xs)[i] = xp[i];
    __syncthreads();
    const int o = threadIdx.x;
    if (o < 56) {
        float acc[9];
        const float b = bc[o];
        #pragma unroll
        for (int p = 0; p < 9; p++) acc[p] = b;
        for (int i = 0; i < 81; i++) {
            float4 wv = *(const float4*)(Wc + o * 324 + i * 4);
            const float* xi = xs + i * 16;
            #pragma unroll
            for (int py = 0; py < 3; py++)
                #pragma unroll
                for (int px = 0; px < 3; px++) {
                    int p = py * 3 + px;
                    acc[p] += xi[py * 4 + px]     * wv.x + xi[py * 4 + px + 1]     * wv.y
                            + xi[(py+1) * 4 + px] * wv.z + xi[(py+1) * 4 + px + 1] * wv.w;
                }
        }
        float* op = g_conv + (size_t)n * 512 + o * 9;
        #pragma unroll
        for (int p = 0; p < 9; p++) op[p] = acc[p];
    } else {
        g_conv[(size_t)n * 512 + 448 + o] = 0.f;
    }
}

// ---------------- pad W_axis [512,504] -> [512,512] --------------------------
__global__ void pad_waxis(const float* __restrict__ W) {
    int idx = blockIdx.x * 256 + threadIdx.x;
    int r = idx >> 9, c = idx & 511;
    g_WaxPad[idx] = (c < 504) ? W[r * 504 + c] : 0.f;
}

// ---------------- SGEMM: C[M,N] (+)= A[M,K] * B[N,K]^T + bias[N] -------------
// inner product in packed f32x2; B pairs loaded pre-packed from smem (adjacent
// floats), only the 8 af-duplicate packs per k-step remain.
template <int ACC>
__global__ __launch_bounds__(256)
void sgemm_nt(const float* __restrict__ A, const float* __restrict__ B,
              const float* __restrict__ bias, float* __restrict__ C,
              int M, int N, int K) {
    __shared__ float As[8][128];
    __shared__ alignas(16) float Bs[8][128];
    const int tid = threadIdx.x;
    const int tx = tid & 15, ty = tid >> 4;
    const int lr = tid >> 1;
    const int lc = (tid & 1) << 2;
    const float* Ap = A + (size_t)(blockIdx.y * 128 + lr) * K + lc;
    const float* Bp = B + (size_t)(blockIdx.x * 128 + lr) * K + lc;
    unsigned long long acc2[8][4] = {};
    for (int k0 = 0; k0 < K; k0 += 8) {
        float4 av = *(const float4*)(Ap + k0);
        float4 bv = *(const float4*)(Bp + k0);
        __syncthreads();
        As[lc+0][lr] = av.x; As[lc+1][lr] = av.y; As[lc+2][lr] = av.z; As[lc+3][lr] = av.w;
        Bs[lc+0][lr] = bv.x; Bs[lc+1][lr] = bv.y; Bs[lc+2][lr] = bv.z; Bs[lc+3][lr] = bv.w;
        __syncthreads();
        #pragma unroll
        for (int k = 0; k < 8; k++) {
            float af[8];
            *(float4*)(af)     = *(const float4*)&As[k][ty * 8];
            *(float4*)(af + 4) = *(const float4*)&As[k][ty * 8 + 4];
            // B pairs are adjacent floats -> load pre-packed
            ulonglong2 b01 = *(const ulonglong2*)&Bs[k][tx * 8];
            ulonglong2 b23 = *(const ulonglong2*)&Bs[k][tx * 8 + 4];
            unsigned long long bfp[4] = { b01.x, b01.y, b23.x, b23.y };
            #pragma unroll
            for (int i = 0; i < 8; i++) {
                unsigned long long afd = pack2(af[i], af[i]);
                #pragma unroll
                for (int j2 = 0; j2 < 4; j2++) fma2(acc2[i][j2], afd, bfp[j2]);
            }
        }
    }
    const int row0 = blockIdx.y * 128 + ty * 8;
    const int col0 = blockIdx.x * 128 + tx * 8;
    float bvals[8];
    #pragma unroll
    for (int j = 0; j < 8; j++) bvals[j] = bias[col0 + j];
    #pragma unroll
    for (int i = 0; i < 8; i++) {
        float* cp = C + (size_t)(row0 + i) * N + col0;
        #pragma unroll
        for (int j = 0; j < 8; j += 4) {
            float2 p0 = unpack2(acc2[i][j/2]);
            float2 p1 = unpack2(acc2[i][j/2 + 1]);
            float4 v;
            v.x = p0.x + bvals[j+0];
            v.y = p0.y + bvals[j+1];
            v.z = p1.x + bvals[j+2];
            v.w = p1.y + bvals[j+3];
            if (ACC) {
                float4 o = *(const float4*)(cp + j);
                v.x += o.x; v.y += o.y; v.z += o.z; v.w += o.w;
            }
            *(float4*)(cp + j) = v;
        }
    }
}

// ---------------- persistent GRU scan, 16-CTA cluster, v4 st.async transport -
// R13 base; activation dependent chain compressed:
//   gi_r/gi_z pre-scaled by 0.5 at prefetch (off-path);
//   n_arg = tr*(0.5hn) + (0.5hn + gi_n)   (both terms parallel with r's MUFU);
//   z*h and (1-z) computed in parallel with n's MUFU -> single FFMA update.
// Dependent chain: fma(4) MUFU(16) fma(4) MUFU(16) fma(4) ~ 44 cyc.
template <int SAVEALL>
__global__ __launch_bounds__(NTHR, 1)
void scan_kernel(const float* __restrict__ Whh, const float* __restrict__ bhh, int steps) {
    __shared__ alignas(16) float hbuf[2][512];
    __shared__ float gh_s[96];
    __shared__ alignas(8) unsigned long long mbar[2];

    const int c   = blockIdx.x;
    const int tid = threadIdx.x;
    const int w   = tid >> 5;
    const int l   = tid & 31;
    const int grp = tid >> 3;          // 0..47 -> rows grp*2, grp*2+1
    const int seg = tid & 7;           // k-segment: elements seg*4 + 32*i + j
    const int r0  = grp * 2, r1 = r0 + 1;
    const int grow0 = (r0 >> 5) * 512 + c * 32 + (r0 & 31);
    const int grow1 = (r1 >> 5) * 512 + c * 32 + (r1 & 31);

    unsigned long long wq0[32], wq1[32];
    #pragma unroll
    for (int i = 0; i < 16; i++) {
        ulonglong2 t0 = *(const ulonglong2*)(Whh + (size_t)grow0 * 512 + seg * 4 + 32 * i);
        ulonglong2 t1 = *(const ulonglong2*)(Whh + (size_t)grow1 * 512 + seg * 4 + 32 * i);
        wq0[2*i] = t0.x; wq0[2*i+1] = t0.y;
        wq1[2*i] = t1.x; wq1[2*i+1] = t1.y;
    }
    const int rowout = grp * 2 + (l & 1);
    const float bh = bhh[(rowout >> 5) * 512 + c * 32 + (rowout & 31)];

    const uint32_t mbase = smem_u32(&mbar[0]);
    if (tid == 0) {
        asm volatile("mbarrier.init.shared.b64 [%0], %1;" :: "r"(mbase),      "r"(1) : "memory");
        asm volatile("mbarrier.init.shared.b64 [%0], %1;" :: "r"(mbase + 8u), "r"(1) : "memory");
        // arm mbar[1] for its first use (wait at t=1): 2048 B total
        asm volatile("mbarrier.arrive.expect_tx.shared.b64 _, [%0], %1;"
                     :: "r"(mbase + 8u), "r"(2048u) : "memory");
    }
    for (int i = tid; i < 2 * 512; i += NTHR) ((float*)hbuf)[i] = 0.f;
    __syncthreads();
    asm volatile("barrier.cluster.arrive.aligned;" ::: "memory");
    asm volatile("barrier.cluster.wait.aligned;"   ::: "memory");

    const float* hb0p = &hbuf[0][0] + seg * 4;
    const float* hb1p = &hbuf[1][0] + seg * 4;

    // warp 0: per-round remote addresses; round r: peer p = (r*4 + (l>>3) + c)&15,
    // quad q = l&7 -> 16 bytes at hbuf + (c*32 + q*4)*4
    uint32_t rb4[4], rm4[4];
    if (w == 0) {
        const uint32_t qoff = smem_u32(&hbuf[0][0]) + (uint32_t)(c * 32 + (l & 7) * 4) * 4u;
        #pragma unroll
        for (int r = 0; r < 4; r++) {
            uint32_t p = (uint32_t)((r * 4 + (l >> 3) + c) & 15);
            rb4[r] = mapa_u32(qoff,  p);
            rm4[r] = mapa_u32(mbase, p);
        }
    }

    float hreg = 0.f;
    unsigned par0 = 0, par1 = 0;

    // gi_r/gi_z held PRE-SCALED by 0.5 (tanh-form sigmoid); gi_n unscaled
    float gi_r = 0.f, gi_z = 0.f, gi_n = 0.f;
    float gn_r = 0.f, gn_z = 0.f, gn_n = 0.f;
    if (w == 0) {
        const float* g0 = g_Gi + (size_t)c * 32 + l;
        gi_r = 0.5f * __ldcs(g0); gi_z = 0.5f * __ldcs(g0 + 512); gi_n = __ldcs(g0 + 1024);
    }

    for (int t = 0; t < steps; t++) {
        if (w == 0 && (t + 1) < steps) {
            const float* gn = g_Gi + (size_t)(t + 1) * 1536 + c * 32 + l;
            gn_r = 0.5f * __ldcs(gn); gn_z = 0.5f * __ldcs(gn + 512); gn_n = __ldcs(gn + 1024);
        }
        // single-waiter: warp 0 waits the mbarrier, bar 2 releases the rest
        if (t > 0) {
            if (w == 0) {
                if (t & 1) { mbar_wait_cta(mbase + 8u, par1); par1 ^= 1; }
                else       { mbar_wait_cta(mbase,      par0); par0 ^= 1; }
            }
            asm volatile("bar.sync 2, %0;" :: "r"(NTHR) : "memory");
        }
        const float* hseg = (t & 1) ? hb1p : hb0p;

        unsigned long long a0 = 0ull, a0b = 0ull, a1 = 0ull, a1b = 0ull;
        #pragma unroll
        for (int i = 0; i < 16; i++) {
            ulonglong2 hv = *(const ulonglong2*)(hseg + 32 * i);
            fma2(a0,  wq0[2*i],   hv.x);
            fma2(a0b, wq0[2*i+1], hv.y);
            fma2(a1,  wq1[2*i],   hv.x);
            fma2(a1b, wq1[2*i+1], hv.y);
        }
        float2 f0 = unpack2(a0), f0b = unpack2(a0b);
        float2 f1 = unpack2(a1), f1b = unpack2(a1b);
        float v0 = (f0.x + f0.y) + (f0b.x + f0b.y);
        float v1 = (f1.x + f1.y) + (f1b.x + f1b.y);
        float u0 = __shfl_xor_sync(0xffffffffu, v0, 1);
        float u1 = __shfl_xor_sync(0xffffffffu, v1, 1);
        float d  = (l & 1) ? (v1 + u1) : (v0 + u0);
        d += __shfl_xor_sync(0xffffffffu, d, 2);
        d += __shfl_xor_sync(0xffffffffu, d, 4);
        if ((l & 6) == 0) gh_s[rowout] = d + bh;

        if (w != 0) {
            // hand gh to warp 0 and park at the next wait immediately
            asm volatile("bar.arrive 1, %0;" :: "r"(NTHR) : "memory");
        } else {
            asm volatile("bar.sync 1, %0;" :: "r"(NTHR) : "memory");   // gh ready

            const float ghr = gh_s[l];
            const float ghz = gh_s[32 + l];
            const float ghn = gh_s[64 + l];
            // r chain: tr = tanh(0.5*ghr + gi_r)         [gi_r pre-halved]
            float tr = tanh_fast(fmaf(0.5f, ghr, gi_r));
            // parallel with r's MUFU:
            float tz = tanh_fast(fmaf(0.5f, ghz, gi_z));  // z gate (independent)
            float p  = 0.5f * ghn;
            float q  = fmaf(0.5f, ghn, gi_n);
            // n chain: n = tanh(r*ghn + gi_n) = tanh(tr*p + q)
            float n  = tanh_fast(fmaf(tr, p, q));
            // parallel with n's MUFU:
            float z   = fmaf(0.5f, tz, 0.5f);
            float zh  = z * hreg;
            float omz = fmaf(-0.5f, tz, 0.5f);
            hreg = fmaf(n, omz, zh);                      // single dependent FFMA

            if (t + 1 < steps) {
                // arm mbar[t&1] for use at t+2 BEFORE any h_{t+1} send
                if (l == 16 && (t + 2) < steps) {
                    asm volatile("mbarrier.arrive.expect_tx.shared.b64 _, [%0], %1;"
                                 :: "r"(mbase + 8u * (uint32_t)(t & 1)), "r"(2048u)
                                 : "memory");
                }
                // gather this lane's quad of h (quad q = l&7) via shfl
                const int qb = (l & 7) * 4;
                const uint32_t h0 = __float_as_uint(__shfl_sync(0xffffffffu, hreg, qb + 0));
                const uint32_t h1 = __float_as_uint(__shfl_sync(0xffffffffu, hreg, qb + 1));
                const uint32_t h2 = __float_as_uint(__shfl_sync(0xffffffffu, hreg, qb + 2));
                const uint32_t h3 = __float_as_uint(__shfl_sync(0xffffffffu, hreg, qb + 3));
                const uint32_t off  = (uint32_t)(((t + 1) & 1) << 11);  // hbuf stride
                const uint32_t boff = (uint32_t)(((t + 1) & 1) << 3);   // mbar stride
                #pragma unroll
                for (int r2 = 0; r2 < 4; r2++) {
                    asm volatile(
                        "st.async.shared::cluster.mbarrier::complete_tx::bytes.v4.b32 "
                        "[%0], {%1, %2, %3, %4}, [%5];"
                        :: "r"(rb4[r2] + off), "r"(h0), "r"(h1), "r"(h2), "r"(h3),
                           "r"(rm4[r2] + boff) : "memory");
                }
            }
            if (SAVEALL || t == steps - 1)
                g_hs[(size_t)t * 512 + c * 32 + l] = hreg;
            gi_r = gn_r; gi_z = gn_z; gi_n = gn_n;
        }
    }
}

// ---------------- decin = relu(feats + enc_final) ----------------------------
__global__ void decin_kernel() {
    int idx = blockIdx.x * 512 + threadIdx.x;
    const float4* f4 = (const float4*)g_feats;
    const float4* e4 = (const float4*)(g_hs + (size_t)8191 * 512);
    float4 f = f4[idx];
    float4 e = e4[idx & 127];
    float4 r;
    r.x = fmaxf(f.x + e.x, 0.f); r.y = fmaxf(f.y + e.y, 0.f);
    r.z = fmaxf(f.z + e.z, 0.f); r.w = fmaxf(f.w + e.w, 0.f);
    ((float4*)g_decin)[idx] = r;
}

// ---------------- out = sigmoid(hs @ W_out^T + b_out) ------------------------
__global__ void out_kernel(const float* __restrict__ Wout, const float* __restrict__ bout,
                           float* __restrict__ out) {
    int row = blockIdx.x * 8 + (threadIdx.x >> 5);
    int l = threadIdx.x & 31;
    const float4* h4 = (const float4*)(g_hs + (size_t)row * 512);
    const float4* w4 = (const float4*)Wout;
    float s = 0.f;
    #pragma unroll
    for (int k = 0; k < 4; k++) {
        float4 h = h4[l + 32 * k], w = w4[l + 32 * k];
        s += h.x * w.x + h.y * w.y + h.z * w.z + h.w * w.w;
    }
    #pragma unroll
    for (int o = 16; o > 0; o >>= 1) s += __shfl_xor_sync(0xffffffffu, s, o);
    if (l == 0) out[row] = sigm(s + bout[0]);
}

// ---------------- launch ------------------------------------------------------
template <int SAVEALL>
static void launch_scan(const float* Whh, const float* bhh, int steps) {
    static int attr_done = 0;
    if (!attr_done) {
        cudaFuncSetAttribute(scan_kernel<SAVEALL>,
                             cudaFuncAttributeNonPortableClusterSizeAllowed, 1);
        attr_done = 1;
    }
    cudaLaunchConfig_t cfg = {};
    cfg.gridDim  = dim3(NCTA, 1, 1);
    cfg.blockDim = dim3(NTHR, 1, 1);
    cfg.dynamicSmemBytes = 0;
    cfg.stream = 0;
    cudaLaunchAttribute attrs[1];
    attrs[0].id = cudaLaunchAttributeClusterDimension;
    attrs[0].val.clusterDim.x = NCTA;
    attrs[0].val.clusterDim.y = 1;
    attrs[0].val.clusterDim.z = 1;
    cfg.attrs = attrs;
    cfg.numAttrs = 1;
    cudaLaunchKernelEx(&cfg, scan_kernel<SAVEALL>, Whh, bhh, steps);
}

extern "C" void kernel_launch(void* const* d_in, const int* in_sizes, int n_in,
                              void* d_out, int out_size) {
    const float* boxes_feature   = (const float*)d_in[0];
    const float* boxes_box_score = (const float*)d_in[1];
    const float* W_app  = (const float*)d_in[2];
    const float* b_app  = (const float*)d_in[3];
    const float* W_conv = (const float*)d_in[4];
    const float* b_conv = (const float*)d_in[5];
    const float* W_axis = (const float*)d_in[6];
    const float* b_axis = (const float*)d_in[7];
    const float* Wih_e  = (const float*)d_in[8];
    const float* Whh_e  = (const float*)d_in[9];
    const float* bih_e  = (const float*)d_in[10];
    const float* bhh_e  = (const float*)d_in[11];
    const float* Wih_d  = (const float*)d_in[12];
    const float* Whh_d  = (const float*)d_in[13];
    const float* bih_d  = (const float*)d_in[14];
    const float* bhh_d  = (const float*)d_in[15];
    const float* W_out  = (const float*)d_in[16];
    const float* b_out  = (const float*)d_in[17];
    float* out = (float*)d_out;

    conv_kernel<<<NPROP, 64>>>(boxes_box_score, W_conv, b_conv);
    pad_waxis<<<1024, 256>>>(W_axis);

    float* feats = nullptr; cudaGetSymbolAddress((void**)&feats, g_feats);
    float* convp = nullptr; cudaGetSymbolAddress((void**)&convp, g_conv);
    float* waxp  = nullptr; cudaGetSymbolAddress((void**)&waxp,  g_WaxPad);
    float* gi    = nullptr; cudaGetSymbolAddress((void**)&gi,    g_Gi);
    float* decin = nullptr; cudaGetSymbolAddress((void**)&decin, g_decin);

    sgemm_nt<0><<<dim3(4, 64), 256>>>(boxes_feature, W_app, b_app, feats, NPROP, 512, 1024);
    sgemm_nt<1><<<dim3(4, 64), 256>>>(convp, waxp, b_axis, feats, NPROP, 512, 512);

    // encoder (only final h needed)
    sgemm_nt<0><<<dim3(12, 64), 256>>>(feats, Wih_e, bih_e, gi, NPROP, 1536, 512);
    launch_scan<0>(Whh_e, bhh_e, NPROP);

    // decoder (all h needed)
    decin_kernel<<<2048, 512>>>();
    sgemm_nt<0><<<dim3(12, 64), 256>>>(decin, Wih_d, bih_d, gi, NPROP, 1536, 512);
    launch_scan<1>(Whh_d, bhh_d, NPROP);

    out_kernel<<<1024, 256>>>(W_out, b_out, out);
}

// round 15
// speedup vs baseline: 1.2358x; 1.2358x over previous
#include <cuda_runtime.h>
#include <cstdint>

#define NPROP 8192
#define HID   512
#define NCTA  16          // cluster size for the scan
#define NTHR  384         // 12 warps, unified (warp 0 also does act+send)

// ---------------- scratch (static device arrays; no runtime alloc) ----------
__device__ float g_conv [(size_t)NPROP * 512];      // conv output, padded 504->512
__device__ float g_feats[(size_t)NPROP * 512];
__device__ float g_Gi   [(size_t)NPROP * 1536];     // reused for encoder then decoder
__device__ float g_hs   [(size_t)NPROP * 512];      // h per step (decoder) / final (enc)
__device__ float g_decin[(size_t)NPROP * 512];
__device__ float g_WaxPad[512 * 512];               // W_axis padded 504 -> 512 cols

// ---------------- helpers ---------------------------------------------------
__device__ __forceinline__ void fma2(unsigned long long& acc, unsigned long long a,
                                     unsigned long long b) {
    asm("fma.rn.f32x2 %0, %1, %2, %0;" : "+l"(acc) : "l"(a), "l"(b));
}
__device__ __forceinline__ unsigned long long pack2(float lo, float hi) {
    unsigned long long v;
    asm("mov.b64 %0, {%1, %2};" : "=l"(v) : "f"(lo), "f"(hi));
    return v;
}
__device__ __forceinline__ float2 unpack2(unsigned long long v) {
    float2 r; asm("mov.b64 {%0,%1}, %2;" : "=f"(r.x), "=f"(r.y) : "l"(v)); return r;
}
// accurate sigmoid (out_kernel, off critical path)
__device__ __forceinline__ float sigm(float x) {
    float e = __expf(-x);
    return __fdividef(1.f, 1.f + e);
}
// fast tanh (scan critical path): single MUFU.TANH
__device__ __forceinline__ float tanh_fast(float x) {
    float y;
    asm("tanh.approx.f32 %0, %1;" : "=f"(y) : "f"(x));
    return y;
}
__device__ __forceinline__ uint32_t smem_u32(const void* p) {
    uint32_t a;
    asm("{ .reg .u64 t; cvta.to.shared.u64 t, %1; cvt.u32.u64 %0, t; }" : "=r"(a) : "l"(p));
    return a;
}
__device__ __forceinline__ uint32_t mapa_u32(uint32_t local, uint32_t rank) {
    uint32_t r;
    asm("mapa.shared::cluster.u32 %0, %1, %2;" : "=r"(r) : "r"(local), "r"(rank));
    return r;
}
// local-scope acquire wait (data arrives via st.async + complete_tx)
__device__ __forceinline__ void mbar_wait_cta(uint32_t mbar, unsigned parity) {
    asm volatile(
        "{\n\t.reg .pred P;\n\t"
        "WLOOP_%=:\n\t"
        "mbarrier.try_wait.parity.acquire.cta.shared::cta.b64 P, [%0], %1, 0x989680;\n\t"
        "@P bra.uni WDONE_%=;\n\t"
        "bra.uni WLOOP_%=;\n\t"
        "WDONE_%=:\n\t}"
        :: "r"(mbar), "r"(parity) : "memory");
}

// ---------------- conv: [N,81,4,4] (x) [56,81,2,2] -> [N,504] (+pad to 512) --
__global__ void conv_kernel(const float* __restrict__ x, const float* __restrict__ Wc,
                            const float* __restrict__ bc) {
    __shared__ float xs[1296];
    const int n = blockIdx.x;
    const float4* xp = (const float4*)(x + (size_t)n * 1296);
    for (int i = threadIdx.x; i < 324; i += 64) ((float4*)xs)[i] = xp[i];
    __syncthreads();
    const int o = threadIdx.x;
    if (o < 56) {
        float acc[9];
        const float b = bc[o];
        #pragma unroll
        for (int p = 0; p < 9; p++) acc[p] = b;
        for (int i = 0; i < 81; i++) {
            float4 wv = *(const float4*)(Wc + o * 324 + i * 4);
            const float* xi = xs + i * 16;
            #pragma unroll
            for (int py = 0; py < 3; py++)
                #pragma unroll
                for (int px = 0; px < 3; px++) {
                    int p = py * 3 + px;
                    acc[p] += xi[py * 4 + px]     * wv.x + xi[py * 4 + px + 1]     * wv.y
                            + xi[(py+1) * 4 + px] * wv.z + xi[(py+1) * 4 + px + 1] * wv.w;
                }
        }
        float* op = g_conv + (size_t)n * 512 + o * 9;
        #pragma unroll
        for (int p = 0; p < 9; p++) op[p] = acc[p];
    } else {
        g_conv[(size_t)n * 512 + 448 + o] = 0.f;
    }
}

// ---------------- pad W_axis [512,504] -> [512,512] --------------------------
__global__ void pad_waxis(const float* __restrict__ W) {
    int idx = blockIdx.x * 256 + threadIdx.x;
    int r = idx >> 9, c = idx & 511;
    g_WaxPad[idx] = (c < 504) ? W[r * 504 + c] : 0.f;
}

// ---------------- SGEMM: C[M,N] (+)= A[M,K] * B[N,K]^T + bias[N] -------------
// inner product in packed f32x2; B pairs loaded pre-packed from smem (adjacent
// floats), only the 8 af-duplicate packs per k-step remain.
template <int ACC>
__global__ __launch_bounds__(256)
void sgemm_nt(const float* __restrict__ A, const float* __restrict__ B,
              const float* __restrict__ bias, float* __restrict__ C,
              int M, int N, int K) {
    __shared__ float As[8][128];
    __shared__ alignas(16) float Bs[8][128];
    const int tid = threadIdx.x;
    const int tx = tid & 15, ty = tid >> 4;
    const int lr = tid >> 1;
    const int lc = (tid & 1) << 2;
    const float* Ap = A + (size_t)(blockIdx.y * 128 + lr) * K + lc;
    const float* Bp = B + (size_t)(blockIdx.x * 128 + lr) * K + lc;
    unsigned long long acc2[8][4] = {};
    for (int k0 = 0; k0 < K; k0 += 8) {
        float4 av = *(const float4*)(Ap + k0);
        float4 bv = *(const float4*)(Bp + k0);
        __syncthreads();
        As[lc+0][lr] = av.x; As[lc+1][lr] = av.y; As[lc+2][lr] = av.z; As[lc+3][lr] = av.w;
        Bs[lc+0][lr] = bv.x; Bs[lc+1][lr] = bv.y; Bs[lc+2][lr] = bv.z; Bs[lc+3][lr] = bv.w;
        __syncthreads();
        #pragma unroll
        for (int k = 0; k < 8; k++) {
            float af[8];
            *(float4*)(af)     = *(const float4*)&As[k][ty * 8];
            *(float4*)(af + 4) = *(const float4*)&As[k][ty * 8 + 4];
            ulonglong2 b01 = *(const ulonglong2*)&Bs[k][tx * 8];
            ulonglong2 b23 = *(const ulonglong2*)&Bs[k][tx * 8 + 4];
            unsigned long long bfp[4] = { b01.x, b01.y, b23.x, b23.y };
            #pragma unroll
            for (int i = 0; i < 8; i++) {
                unsigned long long afd = pack2(af[i], af[i]);
                #pragma unroll
                for (int j2 = 0; j2 < 4; j2++) fma2(acc2[i][j2], afd, bfp[j2]);
            }
        }
    }
    const int row0 = blockIdx.y * 128 + ty * 8;
    const int col0 = blockIdx.x * 128 + tx * 8;
    float bvals[8];
    #pragma unroll
    for (int j = 0; j < 8; j++) bvals[j] = bias[col0 + j];
    #pragma unroll
    for (int i = 0; i < 8; i++) {
        float* cp = C + (size_t)(row0 + i) * N + col0;
        #pragma unroll
        for (int j = 0; j < 8; j += 4) {
            float2 p0 = unpack2(acc2[i][j/2]);
            float2 p1 = unpack2(acc2[i][j/2 + 1]);
            float4 v;
            v.x = p0.x + bvals[j+0];
            v.y = p0.y + bvals[j+1];
            v.z = p1.x + bvals[j+2];
            v.w = p1.y + bvals[j+3];
            if (ACC) {
                float4 o = *(const float4*)(cp + j);
                v.x += o.x; v.y += o.y; v.z += o.z; v.w += o.w;
            }
            *(float4*)(cp + j) = v;
        }
    }
}

// ---------------- persistent GRU scan, 16-CTA cluster, v4 st.async transport -
// R13 base (raw Gi prefetch, consumed ONE FULL STEP later via register swap —
// keeps DRAM latency off the critical path; R14's prefetch-time scaling broke
// this and is reverted). Act chain compressed with CONSUMPTION-time scaling:
// sr/sz depend only on last-step registers -> scheduled before/parallel with
// the gh_s LDS; dependent chain stays fma-MUFU-fma-MUFU-fma (~44 cyc).
template <int SAVEALL>
__global__ __launch_bounds__(NTHR, 1)
void scan_kernel(const float* __restrict__ Whh, const float* __restrict__ bhh, int steps) {
    __shared__ alignas(16) float hbuf[2][512];
    __shared__ float gh_s[96];
    __shared__ alignas(8) unsigned long long mbar[2];

    const int c   = blockIdx.x;
    const int tid = threadIdx.x;
    const int w   = tid >> 5;
    const int l   = tid & 31;
    const int grp = tid >> 3;          // 0..47 -> rows grp*2, grp*2+1
    const int seg = tid & 7;           // k-segment: elements seg*4 + 32*i + j
    const int r0  = grp * 2, r1 = r0 + 1;
    const int grow0 = (r0 >> 5) * 512 + c * 32 + (r0 & 31);
    const int grow1 = (r1 >> 5) * 512 + c * 32 + (r1 & 31);

    unsigned long long wq0[32], wq1[32];
    #pragma unroll
    for (int i = 0; i < 16; i++) {
        ulonglong2 t0 = *(const ulonglong2*)(Whh + (size_t)grow0 * 512 + seg * 4 + 32 * i);
        ulonglong2 t1 = *(const ulonglong2*)(Whh + (size_t)grow1 * 512 + seg * 4 + 32 * i);
        wq0[2*i] = t0.x; wq0[2*i+1] = t0.y;
        wq1[2*i] = t1.x; wq1[2*i+1] = t1.y;
    }
    const int rowout = grp * 2 + (l & 1);
    const float bh = bhh[(rowout >> 5) * 512 + c * 32 + (rowout & 31)];

    const uint32_t mbase = smem_u32(&mbar[0]);
    if (tid == 0) {
        asm volatile("mbarrier.init.shared.b64 [%0], %1;" :: "r"(mbase),      "r"(1) : "memory");
        asm volatile("mbarrier.init.shared.b64 [%0], %1;" :: "r"(mbase + 8u), "r"(1) : "memory");
        // arm mbar[1] for its first use (wait at t=1): 2048 B total
        asm volatile("mbarrier.arrive.expect_tx.shared.b64 _, [%0], %1;"
                     :: "r"(mbase + 8u), "r"(2048u) : "memory");
    }
    for (int i = tid; i < 2 * 512; i += NTHR) ((float*)hbuf)[i] = 0.f;
    __syncthreads();
    asm volatile("barrier.cluster.arrive.aligned;" ::: "memory");
    asm volatile("barrier.cluster.wait.aligned;"   ::: "memory");

    const float* hb0p = &hbuf[0][0] + seg * 4;
    const float* hb1p = &hbuf[1][0] + seg * 4;

    // warp 0: per-round remote addresses; round r: peer p = (r*4 + (l>>3) + c)&15,
    // quad q = l&7 -> 16 bytes at hbuf + (c*32 + q*4)*4
    uint32_t rb4[4], rm4[4];
    if (w == 0) {
        const uint32_t qoff = smem_u32(&hbuf[0][0]) + (uint32_t)(c * 32 + (l & 7) * 4) * 4u;
        #pragma unroll
        for (int r = 0; r < 4; r++) {
            uint32_t p = (uint32_t)((r * 4 + (l >> 3) + c) & 15);
            rb4[r] = mapa_u32(qoff,  p);
            rm4[r] = mapa_u32(mbase, p);
        }
    }

    float hreg = 0.f;
    unsigned par0 = 0, par1 = 0;

    // raw Gi prefetch (NO scaling here — loads stay unconsumed for a full step)
    float gi_r = 0.f, gi_z = 0.f, gi_n = 0.f;
    float gn_r = 0.f, gn_z = 0.f, gn_n = 0.f;
    if (w == 0) {
        const float* g0 = g_Gi + (size_t)c * 32 + l;
        gi_r = __ldcs(g0); gi_z = __ldcs(g0 + 512); gi_n = __ldcs(g0 + 1024);
    }

    for (int t = 0; t < steps; t++) {
        if (w == 0 && (t + 1) < steps) {
            const float* gn = g_Gi + (size_t)(t + 1) * 1536 + c * 32 + l;
            gn_r = __ldcs(gn); gn_z = __ldcs(gn + 512); gn_n = __ldcs(gn + 1024);
        }
        // single-waiter: warp 0 waits the mbarrier, bar 2 releases the rest
        if (t > 0) {
            if (w == 0) {
                if (t & 1) { mbar_wait_cta(mbase + 8u, par1); par1 ^= 1; }
                else       { mbar_wait_cta(mbase,      par0); par0 ^= 1; }
            }
            asm volatile("bar.sync 2, %0;" :: "r"(NTHR) : "memory");
        }
        const float* hseg = (t & 1) ? hb1p : hb0p;

        unsigned long long a0 = 0ull, a0b = 0ull, a1 = 0ull, a1b = 0ull;
        #pragma unroll
        for (int i = 0; i < 16; i++) {
            ulonglong2 hv = *(const ulonglong2*)(hseg + 32 * i);
            fma2(a0,  wq0[2*i],   hv.x);
            fma2(a0b, wq0[2*i+1], hv.y);
            fma2(a1,  wq1[2*i],   hv.x);
            fma2(a1b, wq1[2*i+1], hv.y);
        }
        float2 f0 = unpack2(a0), f0b = unpack2(a0b);
        float2 f1 = unpack2(a1), f1b = unpack2(a1b);
        float v0 = (f0.x + f0.y) + (f0b.x + f0b.y);
        float v1 = (f1.x + f1.y) + (f1b.x + f1b.y);
        float u0 = __shfl_xor_sync(0xffffffffu, v0, 1);
        float u1 = __shfl_xor_sync(0xffffffffu, v1, 1);
        float d  = (l & 1) ? (v1 + u1) : (v0 + u0);
        d += __shfl_xor_sync(0xffffffffu, d, 2);
        d += __shfl_xor_sync(0xffffffffu, d, 4);
        if ((l & 6) == 0) gh_s[rowout] = d + bh;

        if (w != 0) {
            // hand gh to warp 0 and park at the next wait immediately
            asm volatile("bar.arrive 1, %0;" :: "r"(NTHR) : "memory");
        } else {
            // scale off the dependent chain: depends only on last-step regs,
            // schedulable before/around the barrier
            float sr = 0.5f * gi_r;
            float sz = 0.5f * gi_z;
            asm volatile("bar.sync 1, %0;" :: "r"(NTHR) : "memory");   // gh ready

            const float ghr = gh_s[l];
            const float ghz = gh_s[32 + l];
            const float ghn = gh_s[64 + l];
            float tr = tanh_fast(fmaf(0.5f, ghr, sr));
            // parallel with r's MUFU:
            float tz = tanh_fast(fmaf(0.5f, ghz, sz));
            float p  = 0.5f * ghn;
            float q  = fmaf(0.5f, ghn, gi_n);
            float n  = tanh_fast(fmaf(tr, p, q));
            // parallel with n's MUFU:
            float z   = fmaf(0.5f, tz, 0.5f);
            float zh  = z * hreg;
            float omz = fmaf(-0.5f, tz, 0.5f);
            hreg = fmaf(n, omz, zh);                      // single dependent FFMA

            if (t + 1 < steps) {
                // arm mbar[t&1] for use at t+2 BEFORE any h_{t+1} send
                if (l == 16 && (t + 2) < steps) {
                    asm volatile("mbarrier.arrive.expect_tx.shared.b64 _, [%0], %1;"
                                 :: "r"(mbase + 8u * (uint32_t)(t & 1)), "r"(2048u)
                                 : "memory");
                }
                // gather this lane's quad of h (quad q = l&7) via shfl
                const int qb = (l & 7) * 4;
                const uint32_t h0 = __float_as_uint(__shfl_sync(0xffffffffu, hreg, qb + 0));
                const uint32_t h1 = __float_as_uint(__shfl_sync(0xffffffffu, hreg, qb + 1));
                const uint32_t h2 = __float_as_uint(__shfl_sync(0xffffffffu, hreg, qb + 2));
                const uint32_t h3 = __float_as_uint(__shfl_sync(0xffffffffu, hreg, qb + 3));
                const uint32_t off  = (uint32_t)(((t + 1) & 1) << 11);  // hbuf stride
                const uint32_t boff = (uint32_t)(((t + 1) & 1) << 3);   // mbar stride
                #pragma unroll
                for (int r2 = 0; r2 < 4; r2++) {
                    asm volatile(
                        "st.async.shared::cluster.mbarrier::complete_tx::bytes.v4.b32 "
                        "[%0], {%1, %2, %3, %4}, [%5];"
                        :: "r"(rb4[r2] + off), "r"(h0), "r"(h1), "r"(h2), "r"(h3),
                           "r"(rm4[r2] + boff) : "memory");
                }
            }
            if (SAVEALL || t == steps - 1)
                g_hs[(size_t)t * 512 + c * 32 + l] = hreg;
            gi_r = gn_r; gi_z = gn_z; gi_n = gn_n;   // pure register renames
        }
    }
}

// ---------------- decin = relu(feats + enc_final) ----------------------------
__global__ void decin_kernel() {
    int idx = blockIdx.x * 512 + threadIdx.x;
    const float4* f4 = (const float4*)g_feats;
    const float4* e4 = (const float4*)(g_hs + (size_t)8191 * 512);
    float4 f = f4[idx];
    float4 e = e4[idx & 127];
    float4 r;
    r.x = fmaxf(f.x + e.x, 0.f); r.y = fmaxf(f.y + e.y, 0.f);
    r.z = fmaxf(f.z + e.z, 0.f); r.w = fmaxf(f.w + e.w, 0.f);
    ((float4*)g_decin)[idx] = r;
}

// ---------------- out = sigmoid(hs @ W_out^T + b_out) ------------------------
__global__ void out_kernel(const float* __restrict__ Wout, const float* __restrict__ bout,
                           float* __restrict__ out) {
    int row = blockIdx.x * 8 + (threadIdx.x >> 5);
    int l = threadIdx.x & 31;
    const float4* h4 = (const float4*)(g_hs + (size_t)row * 512);
    const float4* w4 = (const float4*)Wout;
    float s = 0.f;
    #pragma unroll
    for (int k = 0; k < 4; k++) {
        float4 h = h4[l + 32 * k], w = w4[l + 32 * k];
        s += h.x * w.x + h.y * w.y + h.z * w.z + h.w * w.w;
    }
    #pragma unroll
    for (int o = 16; o > 0; o >>= 1) s += __shfl_xor_sync(0xffffffffu, s, o);
    if (l == 0) out[row] = sigm(s + bout[0]);
}

// ---------------- launch ------------------------------------------------------
template <int SAVEALL>
static void launch_scan(const float* Whh, const float* bhh, int steps) {
    static int attr_done = 0;
    if (!attr_done) {
        cudaFuncSetAttribute(scan_kernel<SAVEALL>,
                             cudaFuncAttributeNonPortableClusterSizeAllowed, 1);
        attr_done = 1;
    }
    cudaLaunchConfig_t cfg = {};
    cfg.gridDim  = dim3(NCTA, 1, 1);
    cfg.blockDim = dim3(NTHR, 1, 1);
    cfg.dynamicSmemBytes = 0;
    cfg.stream = 0;
    cudaLaunchAttribute attrs[1];
    attrs[0].id = cudaLaunchAttributeClusterDimension;
    attrs[0].val.clusterDim.x = NCTA;
    attrs[0].val.clusterDim.y = 1;
    attrs[0].val.clusterDim.z = 1;
    cfg.attrs = attrs;
    cfg.numAttrs = 1;
    cudaLaunchKernelEx(&cfg, scan_kernel<SAVEALL>, Whh, bhh, steps);
}

extern "C" void kernel_launch(void* const* d_in, const int* in_sizes, int n_in,
                              void* d_out, int out_size) {
    const float* boxes_feature   = (const float*)d_in[0];
    const float* boxes_box_score = (const float*)d_in[1];
    const float* W_app  = (const float*)d_in[2];
    const float* b_app  = (const float*)d_in[3];
    const float* W_conv = (const float*)d_in[4];
    const float* b_conv = (const float*)d_in[5];
    const float* W_axis = (const float*)d_in[6];
    const float* b_axis = (const float*)d_in[7];
    const float* Wih_e  = (const float*)d_in[8];
    const float* Whh_e  = (const float*)d_in[9];
    const float* bih_e  = (const float*)d_in[10];
    const float* bhh_e  = (const float*)d_in[11];
    const float* Wih_d  = (const float*)d_in[12];
    const float* Whh_d  = (const float*)d_in[13];
    const float* bih_d  = (const float*)d_in[14];
    const float* bhh_d  = (const float*)d_in[15];
    const float* W_out  = (const float*)d_in[16];
    const float* b_out  = (const float*)d_in[17];
    float* out = (float*)d_out;

    conv_kernel<<<NPROP, 64>>>(boxes_box_score, W_conv, b_conv);
    pad_waxis<<<1024, 256>>>(W_axis);

    float* feats = nullptr; cudaGetSymbolAddress((void**)&feats, g_feats);
    float* convp = nullptr; cudaGetSymbolAddress((void**)&convp, g_conv);
    float* waxp  = nullptr; cudaGetSymbolAddress((void**)&waxp,  g_WaxPad);
    float* gi    = nullptr; cudaGetSymbolAddress((void**)&gi,    g_Gi);
    float* decin = nullptr; cudaGetSymbolAddress((void**)&decin, g_decin);

    sgemm_nt<0><<<dim3(4, 64), 256>>>(boxes_feature, W_app, b_app, feats, NPROP, 512, 1024);
    sgemm_nt<1><<<dim3(4, 64), 256>>>(convp, waxp, b_axis, feats, NPROP, 512, 512);

    // encoder (only final h needed)
    sgemm_nt<0><<<dim3(12, 64), 256>>>(feats, Wih_e, bih_e, gi, NPROP, 1536, 512);
    launch_scan<0>(Whh_e, bhh_e, NPROP);

    // decoder (all h needed)
    decin_kernel<<<2048, 512>>>();
    sgemm_nt<0><<<dim3(12, 64), 256>>>(decin, Wih_d, bih_d, gi, NPROP, 1536, 512);
    launch_scan<1>(Whh_d, bhh_d, NPROP);

    out_kernel<<<1024, 256>>>(W_out, b_out, out);
}